// round 13
// baseline (speedup 1.0000x reference)
#include <cuda_runtime.h>

// Correlation cost volume (FlowNet-style), MAX_DISP=4 (81 displacements).
// first, second: [B=4, C=128, H=128, W=192] fp32.  out: [B, 81, H, W] fp32,
// out[b,(dy+4)*9+(dx+4),y,x] = (1/C) * sum_c first[b,c,y,x]*second[b,c,y+dy,x+dx]
//
// v9: R7's exact tile + compute body (best: 72.2us), but the cp.async pipeline
// is 4 buffers of CCH=4 (same 78.8 KB total): 2 stages always in flight,
// half-size issue bursts, one barrier per stage (race-free at distance 4).

namespace {
constexpr int Bb = 4, Cc = 128, Hh = 128, Ww = 192;
constexpr int PXT = 4;             // pixels per thread along x
constexpr int GX  = 16;            // thread columns
constexpr int TX  = GX * PXT;      // 64
constexpr int TY  = 8;
constexpr int NT  = GX * TY;       // 128 threads/block
constexpr int CCH = 4;             // channels per stage (was 8)
constexpr int NST = Cc / CCH;      // 32 stages
constexpr int NBUF = 4;            // pipeline buffers (2 stages in flight)
constexpr int SROWS = TY + 2;      // 10 second rows per dy-group of 3
constexpr int SW  = TX + 8;        // 72 floats per second row
constexpr int SROW_V4 = SW / 4;    // 18
constexpr int XT  = Ww / TX;       // 3
constexpr int YT  = Hh / TY;       // 16
constexpr int SEC_F = CCH * SROWS * SW;   // 2880 floats
constexpr int FST_F = CCH * TY * TX;      // 2048 floats
constexpr int BUF_F = SEC_F + FST_F;      // 4928 floats per buffer
constexpr unsigned SMEM_BYTES = (unsigned)NBUF * BUF_F * 4u;  // 78848 B
constexpr int NBLOCKS = Bb * XT * YT * 3;  // 576 (1.95 waves @ 2 blocks/SM)
constexpr int SEC_V4 = SEC_F / 4;          // 720
constexpr int SEC_SLOTS = 6;               // 5 full + 80-thread tail
constexpr int TAIL = SEC_V4 - 5 * NT;      // 80
constexpr unsigned CH_STRIDE = (unsigned)CCH * Hh * Ww * 4u;   // bytes per stage
constexpr unsigned PLANE = (unsigned)Hh * Ww * 4u;             // one channel plane
}  // namespace

__device__ __forceinline__ void cp16(unsigned sdst, const char* gsrc, unsigned sz) {
    asm volatile("cp.async.cg.shared.global [%0], [%1], 16, %2;\n"
                 :: "r"(sdst), "l"(gsrc), "r"(sz) : "memory");
}
__device__ __forceinline__ unsigned long long pack2(float x, float y) {
    unsigned long long r;
    asm("mov.b64 %0, {%1, %2};" : "=l"(r) : "f"(x), "f"(y));
    return r;
}
__device__ __forceinline__ void ffma2(unsigned long long& d,
                                      unsigned long long a, unsigned long long b) {
    asm("fma.rn.f32x2 %0, %1, %2, %0;" : "+l"(d) : "l"(a), "l"(b));
}
__device__ __forceinline__ void unpack2(unsigned long long v, float& lo, float& hi) {
    asm("mov.b64 {%0, %1}, %2;" : "=f"(lo), "=f"(hi) : "l"(v));
}

__global__ __launch_bounds__(NT, 2)
void FunctionCorrelation_17282948399394_kernel(
    const float* __restrict__ first,
    const float* __restrict__ second,
    float* __restrict__ out)
{
    extern __shared__ float smem[];
    const unsigned smem_u32 = (unsigned)__cvta_generic_to_shared(smem);

    const int tx  = threadIdx.x;          // 0..15
    const int ty  = threadIdx.y;          // 0..7
    const int tid = ty * GX + tx;         // 0..127

    int t = blockIdx.x;
    const int g  = t % 3;  t /= 3;        // dy group: dy in {3g-4,3g-3,3g-2}
    const int xt = t % XT; t /= XT;
    const int yt = t % YT; t /= YT;
    const int b  = t;

    const int x0  = xt * TX;
    const int y0  = yt * TY;
    const int ys0 = y0 + 3 * g - 4;

    // ---- precompute second-tile load slots (stage-0 byte offsets) -----------
    unsigned secOff[SEC_SLOTS];
    unsigned vmask = 0;                   // bit s set -> in-bounds (sz=16)
#pragma unroll
    for (int s = 0; s < SEC_SLOTS; s++) {
        const int i = s * NT + tid;
        unsigned off = 0;
        if (i < SEC_V4) {
            const int ch  = i / (SROWS * SROW_V4);   // 0..3 within stage
            const int rem = i - ch * (SROWS * SROW_V4);
            const int r   = rem / SROW_V4;
            const int k   = rem - r * SROW_V4;
            const int gy  = ys0 + r;
            const int gx  = x0 - 4 + 4 * k;
            if ((unsigned)gy < (unsigned)Hh && (unsigned)gx < (unsigned)Ww) {
                off = (unsigned)((((b * Cc + ch) * Hh + gy) * Ww + gx) * 4);
                vmask |= 1u << s;
            }
        }
        secOff[s] = off;
    }
    // first tile: slot s == channel s (one 128-float4 plane tile per slot)
    const int frr = tid >> 4;             // row 0..7
    const int fkk = tid & 15;             // float4 col 0..15
    const unsigned fstOff0 =
        (unsigned)(((b * Cc * Hh + (y0 + frr)) * Ww + x0 + 4 * fkk) * 4);

    const char* secP = (const char*)second;
    const char* fstP = (const char*)first;

    auto issue_stage = [&](int buf, const char* sp, const char* fp) {
        const unsigned sbase = smem_u32 + (unsigned)buf * (BUF_F * 4u);
#pragma unroll
        for (int s = 0; s < SEC_SLOTS; s++) {
            if (s < SEC_SLOTS - 1 || tid < TAIL)
                cp16(sbase + (unsigned)(s * NT + tid) * 16u, sp + secOff[s],
                     ((vmask >> s) & 1u) ? 16u : 0u);
        }
        const unsigned fbase = sbase + (unsigned)SEC_F * 4u;
#pragma unroll
        for (int s = 0; s < CCH; s++) {
            cp16(fbase + (unsigned)(s * NT + tid) * 16u,
                 fp + fstOff0 + (unsigned)s * PLANE, 16u);
        }
        asm volatile("cp.async.commit_group;" ::: "memory");
    };

    // ---- accumulators (identical layout to R7) ------------------------------
    unsigned long long acc2[3][5][2];   // even dx=2q: [j][q][pixel-pair]
    float acco[3][4][4];                // odd dx=2o+1: [j][o][pixel]
#pragma unroll
    for (int j = 0; j < 3; j++) {
#pragma unroll
        for (int q = 0; q < 5; q++) { acc2[j][q][0] = 0ull; acc2[j][q][1] = 0ull; }
#pragma unroll
        for (int o = 0; o < 4; o++)
#pragma unroll
            for (int p = 0; p < 4; p++) acco[j][o][p] = 0.f;
    }

    // ---- 4-buffer pipelined main loop (2 stages in flight) ------------------
    issue_stage(0, secP, fstP);  secP += CH_STRIDE;  fstP += CH_STRIDE;
    issue_stage(1, secP, fstP);  secP += CH_STRIDE;  fstP += CH_STRIDE;
    issue_stage(2, secP, fstP);  secP += CH_STRIDE;  fstP += CH_STRIDE;

#pragma unroll 1
    for (int st = 0; st < NST; st++) {
        // wait for stage st (keep up to 2 newer groups in flight)
        if (st < NST - 2)
            asm volatile("cp.async.wait_group 2;" ::: "memory");
        else if (st == NST - 2)
            asm volatile("cp.async.wait_group 1;" ::: "memory");
        else
            asm volatile("cp.async.wait_group 0;" ::: "memory");
        // single barrier per stage: after it, everyone is done reading buffer
        // (st-1)&3 == (st+3)&3, so refilling it below is race-free.
        __syncthreads();

        if (st + 3 < NST) {
            issue_stage((st + 3) & 3, secP, fstP);
            secP += CH_STRIDE;  fstP += CH_STRIDE;
        }

        const float4* secb = (const float4*)(smem + (st & 3) * BUF_F);
        const float4* fstb = (const float4*)(smem + (st & 3) * BUF_F + SEC_F);

#pragma unroll
        for (int ch = 0; ch < CCH; ch++) {
            const float4 f = fstb[(ch * TY + ty) * (TX / 4) + tx];
            const unsigned long long fp0 = pack2(f.x, f.y);
            const unsigned long long fp1 = pack2(f.z, f.w);
#pragma unroll
            for (int j = 0; j < 3; j++) {
                const float4* sr = secb + (ch * SROWS + ty + j) * SROW_V4 + tx;
                const float4 a = sr[0], c = sr[1], e = sr[2];
                // s[0..11] = a.x a.y a.z a.w  c.x c.y c.z c.w  e.x e.y e.z e.w
                const unsigned long long P0 = pack2(a.x, a.y);
                const unsigned long long P1 = pack2(a.z, a.w);
                const unsigned long long P2 = pack2(c.x, c.y);
                const unsigned long long P3 = pack2(c.z, c.w);
                const unsigned long long P4 = pack2(e.x, e.y);
                const unsigned long long P5 = pack2(e.z, e.w);
                // even dx=2q: pair0 (p0,p1) uses P_q, pair1 (p2,p3) uses P_{q+1}
                ffma2(acc2[j][0][0], fp0, P0);  ffma2(acc2[j][0][1], fp1, P1);
                ffma2(acc2[j][1][0], fp0, P1);  ffma2(acc2[j][1][1], fp1, P2);
                ffma2(acc2[j][2][0], fp0, P2);  ffma2(acc2[j][2][1], fp1, P3);
                ffma2(acc2[j][3][0], fp0, P3);  ffma2(acc2[j][3][1], fp1, P4);
                ffma2(acc2[j][4][0], fp0, P4);  ffma2(acc2[j][4][1], fp1, P5);
                // odd dx=2o+1: acco[j][o][p] += f[p] * s[2o+1+p]
                acco[j][0][0] += f.x * a.y;  acco[j][0][1] += f.y * a.z;
                acco[j][0][2] += f.z * a.w;  acco[j][0][3] += f.w * c.x;
                acco[j][1][0] += f.x * a.w;  acco[j][1][1] += f.y * c.x;
                acco[j][1][2] += f.z * c.y;  acco[j][1][3] += f.w * c.z;
                acco[j][2][0] += f.x * c.y;  acco[j][2][1] += f.y * c.z;
                acco[j][2][2] += f.z * c.w;  acco[j][2][3] += f.w * e.x;
                acco[j][3][0] += f.x * c.w;  acco[j][3][1] += f.y * e.x;
                acco[j][3][2] += f.z * e.y;  acco[j][3][3] += f.w * e.z;
            }
        }
    }

    // ---- epilogue: 27 planes x 4 pixels, float4 stores ----------------------
    const float inv = 1.0f / (float)Cc;
    const int x = x0 + tx * PXT;
    const int y = y0 + ty;
#pragma unroll
    for (int j = 0; j < 3; j++) {
        const int dyi = 3 * g + j;
#pragma unroll
        for (int q = 0; q < 5; q++) {              // dx index 2q
            float v0, v1, v2, v3;
            unpack2(acc2[j][q][0], v0, v1);
            unpack2(acc2[j][q][1], v2, v3);
            const int d = dyi * 9 + 2 * q;
            *reinterpret_cast<float4*>(out + ((b * 81 + d) * Hh + y) * Ww + x) =
                make_float4(v0 * inv, v1 * inv, v2 * inv, v3 * inv);
        }
#pragma unroll
        for (int o = 0; o < 4; o++) {              // dx index 2o+1
            const int d = dyi * 9 + 2 * o + 1;
            *reinterpret_cast<float4*>(out + ((b * 81 + d) * Hh + y) * Ww + x) =
                make_float4(acco[j][o][0] * inv, acco[j][o][1] * inv,
                            acco[j][o][2] * inv, acco[j][o][3] * inv);
        }
    }
}

extern "C" void kernel_launch(void* const* d_in, const int* in_sizes, int n_in,
                              void* d_out, int out_size)
{
    const float* first  = (const float*)d_in[0];
    const float* second = (const float*)d_in[1];
    float* out          = (float*)d_out;

    cudaFuncSetAttribute(FunctionCorrelation_17282948399394_kernel,
                         cudaFuncAttributeMaxDynamicSharedMemorySize,
                         (int)SMEM_BYTES);

    dim3 block(GX, TY, 1);
    FunctionCorrelation_17282948399394_kernel<<<NBLOCKS, block, SMEM_BYTES>>>(
        first, second, out);
}

// round 14
// speedup vs baseline: 1.6357x; 1.6357x over previous
#include <cuda_runtime.h>

// Correlation cost volume (FlowNet-style), MAX_DISP=4 (81 displacements).
// first, second: [B=4, C=128, H=128, W=192] fp32.  out: [B, 81, H, W] fp32,
// out[b,(dy+4)*9+(dx+4),y,x] = (1/C) * sum_c first[b,c,y,x]*second[b,c,y+dy,x+dx]
//
// v10: R7 (best: 72.2us) with two latency fixes ONLY:
//  (1) explicit depth-1 register double-buffer across ch: the 10 LDS.128 of
//      ch+1 are issued while the 78 math issues of ch execute (uses the spare
//      ~40 regs of the 255 budget; occupancy unchanged at 2 blocks/SM);
//  (2) one barrier per stage (wait -> barrier -> issue(st+1) -> compute),
//      race-free at pipeline depth 1, same prefetch overlap as R7.

namespace {
constexpr int Bb = 4, Cc = 128, Hh = 128, Ww = 192;
constexpr int PXT = 4;             // pixels per thread along x
constexpr int GX  = 16;            // thread columns
constexpr int TX  = GX * PXT;      // 64
constexpr int TY  = 8;
constexpr int NT  = GX * TY;       // 128 threads/block
constexpr int CCH = 8;             // channels per stage
constexpr int NST = Cc / CCH;      // 16
constexpr int SROWS = TY + 2;      // 10 second rows per dy-group of 3
constexpr int SW  = TX + 8;        // 72 floats per second row
constexpr int SROW_V4 = SW / 4;    // 18
constexpr int XT  = Ww / TX;       // 3
constexpr int YT  = Hh / TY;       // 16
constexpr int SEC_F = CCH * SROWS * SW;   // 5760 floats
constexpr int FST_F = CCH * TY * TX;      // 4096 floats
constexpr int BUF_F = SEC_F + FST_F;      // 9856 floats per pipeline buffer
constexpr unsigned SMEM_BYTES = 2u * BUF_F * 4u;  // 78848 B -> 2 blocks/SM
constexpr int NBLOCKS = Bb * XT * YT * 3;  // 576 (1.95 waves)
constexpr int SEC_V4 = SEC_F / 4;          // 1440 float4 per stage
constexpr int SEC_SLOTS = 12;              // 11 full + 32-thread tail
constexpr unsigned CH_STRIDE = (unsigned)CCH * Hh * Ww * 4u;   // bytes per stage
constexpr unsigned PLANE = (unsigned)Hh * Ww * 4u;             // one channel plane
}  // namespace

__device__ __forceinline__ void cp16(unsigned sdst, const char* gsrc, unsigned sz) {
    asm volatile("cp.async.cg.shared.global [%0], [%1], 16, %2;\n"
                 :: "r"(sdst), "l"(gsrc), "r"(sz) : "memory");
}
__device__ __forceinline__ unsigned long long pack2(float x, float y) {
    unsigned long long r;
    asm("mov.b64 %0, {%1, %2};" : "=l"(r) : "f"(x), "f"(y));
    return r;
}
__device__ __forceinline__ void ffma2(unsigned long long& d,
                                      unsigned long long a, unsigned long long b) {
    asm("fma.rn.f32x2 %0, %1, %2, %0;" : "+l"(d) : "l"(a), "l"(b));
}
__device__ __forceinline__ void unpack2(unsigned long long v, float& lo, float& hi) {
    asm("mov.b64 {%0, %1}, %2;" : "=f"(lo), "=f"(hi) : "l"(v));
}

__global__ __launch_bounds__(NT, 2)
void FunctionCorrelation_17282948399394_kernel(
    const float* __restrict__ first,
    const float* __restrict__ second,
    float* __restrict__ out)
{
    extern __shared__ float smem[];
    const unsigned smem_u32 = (unsigned)__cvta_generic_to_shared(smem);

    const int tx  = threadIdx.x;          // 0..15
    const int ty  = threadIdx.y;          // 0..7
    const int tid = ty * GX + tx;         // 0..127

    int t = blockIdx.x;
    const int g  = t % 3;  t /= 3;        // dy group: dy in {3g-4,3g-3,3g-2}
    const int xt = t % XT; t /= XT;
    const int yt = t % YT; t /= YT;
    const int b  = t;

    const int x0  = xt * TX;
    const int y0  = yt * TY;
    const int ys0 = y0 + 3 * g - 4;

    // ---- precompute second-tile load slots (stage-0 byte offsets) -----------
    unsigned secOff[SEC_SLOTS];
    unsigned vmask = 0;                   // bit s set -> in-bounds (sz=16)
#pragma unroll
    for (int s = 0; s < SEC_SLOTS; s++) {
        const int i = s * NT + tid;
        unsigned off = 0;
        if (i < SEC_V4) {
            const int ch  = i / (SROWS * SROW_V4);
            const int rem = i - ch * (SROWS * SROW_V4);
            const int r   = rem / SROW_V4;
            const int k   = rem - r * SROW_V4;
            const int gy  = ys0 + r;
            const int gx  = x0 - 4 + 4 * k;
            if ((unsigned)gy < (unsigned)Hh && (unsigned)gx < (unsigned)Ww) {
                off = (unsigned)((((b * Cc + ch) * Hh + gy) * Ww + gx) * 4);
                vmask |= 1u << s;
            }
        }
        secOff[s] = off;
    }
    // first tile: 128 threads == one channel plane per slot (ch = slot)
    const int frr = tid >> 4;             // row 0..7
    const int fkk = tid & 15;             // float4 col 0..15
    const unsigned fstOff0 =
        (unsigned)(((b * Cc * Hh + (y0 + frr)) * Ww + x0 + 4 * fkk) * 4);

    const char* secP = (const char*)second;
    const char* fstP = (const char*)first;

    auto issue_stage = [&](int buf, const char* sp, const char* fp) {
        const unsigned sbase = smem_u32 + (unsigned)buf * (BUF_F * 4u);
#pragma unroll
        for (int s = 0; s < SEC_SLOTS; s++) {
            if (s < SEC_SLOTS - 1 || tid < (SEC_V4 - (SEC_SLOTS - 1) * NT))
                cp16(sbase + (unsigned)(s * NT + tid) * 16u, sp + secOff[s],
                     ((vmask >> s) & 1u) ? 16u : 0u);
        }
        const unsigned fbase = sbase + (unsigned)SEC_F * 4u;
#pragma unroll
        for (int s = 0; s < CCH; s++) {
            cp16(fbase + (unsigned)(s * NT + tid) * 16u,
                 fp + fstOff0 + (unsigned)s * PLANE, 16u);
        }
        asm volatile("cp.async.commit_group;" ::: "memory");
    };

    // ---- accumulators (identical layout to R7) ------------------------------
    unsigned long long acc2[3][5][2];   // even dx=2q: [j][q][pixel-pair]
    float acco[3][4][4];                // odd dx=2o+1: [j][o][pixel]
#pragma unroll
    for (int j = 0; j < 3; j++) {
#pragma unroll
        for (int q = 0; q < 5; q++) { acc2[j][q][0] = 0ull; acc2[j][q][1] = 0ull; }
#pragma unroll
        for (int o = 0; o < 4; o++)
#pragma unroll
            for (int p = 0; p < 4; p++) acco[j][o][p] = 0.f;
    }

    // ---- pipelined main loop (1 barrier/stage, depth-1 like R7) -------------
    issue_stage(0, secP, fstP);
    secP += CH_STRIDE; fstP += CH_STRIDE;

#pragma unroll 1
    for (int st = 0; st < NST; st++) {
        asm volatile("cp.async.wait_group 0;" ::: "memory");
        __syncthreads();                       // all warps done reading buf (st+1)&1
        if (st + 1 < NST) {
            issue_stage((st + 1) & 1, secP, fstP);  // overlaps compute below
            secP += CH_STRIDE; fstP += CH_STRIDE;
        }

        const float4* secb = (const float4*)(smem + (st & 1) * BUF_F);
        const float4* fstb = (const float4*)(smem + (st & 1) * BUF_F + SEC_F);

        // register load of one channel's working set: f + 9 second-row vectors
        auto load_s = [&](int ch, float4& f, float4* r) {
            f = fstb[(ch * TY + ty) * (TX / 4) + tx];
#pragma unroll
            for (int j = 0; j < 3; j++) {
                const float4* sr = secb + (ch * SROWS + ty + j) * SROW_V4 + tx;
                r[3 * j + 0] = sr[0];
                r[3 * j + 1] = sr[1];
                r[3 * j + 2] = sr[2];
            }
        };
        auto compute1 = [&](const float4 f, const float4* r) {
            const unsigned long long fp0 = pack2(f.x, f.y);
            const unsigned long long fp1 = pack2(f.z, f.w);
#pragma unroll
            for (int j = 0; j < 3; j++) {
                const float4 a = r[3 * j], c = r[3 * j + 1], e = r[3 * j + 2];
                const unsigned long long P0 = pack2(a.x, a.y);
                const unsigned long long P1 = pack2(a.z, a.w);
                const unsigned long long P2 = pack2(c.x, c.y);
                const unsigned long long P3 = pack2(c.z, c.w);
                const unsigned long long P4 = pack2(e.x, e.y);
                const unsigned long long P5 = pack2(e.z, e.w);
                ffma2(acc2[j][0][0], fp0, P0);  ffma2(acc2[j][0][1], fp1, P1);
                ffma2(acc2[j][1][0], fp0, P1);  ffma2(acc2[j][1][1], fp1, P2);
                ffma2(acc2[j][2][0], fp0, P2);  ffma2(acc2[j][2][1], fp1, P3);
                ffma2(acc2[j][3][0], fp0, P3);  ffma2(acc2[j][3][1], fp1, P4);
                ffma2(acc2[j][4][0], fp0, P4);  ffma2(acc2[j][4][1], fp1, P5);
                acco[j][0][0] += f.x * a.y;  acco[j][0][1] += f.y * a.z;
                acco[j][0][2] += f.z * a.w;  acco[j][0][3] += f.w * c.x;
                acco[j][1][0] += f.x * a.w;  acco[j][1][1] += f.y * c.x;
                acco[j][1][2] += f.z * c.y;  acco[j][1][3] += f.w * c.z;
                acco[j][2][0] += f.x * c.y;  acco[j][2][1] += f.y * c.z;
                acco[j][2][2] += f.z * c.w;  acco[j][2][3] += f.w * e.x;
                acco[j][3][0] += f.x * c.w;  acco[j][3][1] += f.y * e.x;
                acco[j][3][2] += f.z * e.y;  acco[j][3][3] += f.w * e.z;
            }
        };

        // depth-1 register double-buffer over channels: loads of one buffer
        // are always covered by the math of the other.
        float4 fA, fB;
        float4 rA[9], rB[9];
        load_s(0, fA, rA);
#pragma unroll
        for (int chp = 0; chp < CCH / 2; chp++) {
            load_s(2 * chp + 1, fB, rB);
            compute1(fA, rA);
            if (chp < CCH / 2 - 1) load_s(2 * chp + 2, fA, rA);
            compute1(fB, rB);
        }
    }

    // ---- epilogue: 27 planes x 4 pixels, float4 stores ----------------------
    const float inv = 1.0f / (float)Cc;
    const int x = x0 + tx * PXT;
    const int y = y0 + ty;
#pragma unroll
    for (int j = 0; j < 3; j++) {
        const int dyi = 3 * g + j;
#pragma unroll
        for (int q = 0; q < 5; q++) {              // dx index 2q
            float v0, v1, v2, v3;
            unpack2(acc2[j][q][0], v0, v1);
            unpack2(acc2[j][q][1], v2, v3);
            const int d = dyi * 9 + 2 * q;
            *reinterpret_cast<float4*>(out + ((b * 81 + d) * Hh + y) * Ww + x) =
                make_float4(v0 * inv, v1 * inv, v2 * inv, v3 * inv);
        }
#pragma unroll
        for (int o = 0; o < 4; o++) {              // dx index 2o+1
            const int d = dyi * 9 + 2 * o + 1;
            *reinterpret_cast<float4*>(out + ((b * 81 + d) * Hh + y) * Ww + x) =
                make_float4(acco[j][o][0] * inv, acco[j][o][1] * inv,
                            acco[j][o][2] * inv, acco[j][o][3] * inv);
        }
    }
}

extern "C" void kernel_launch(void* const* d_in, const int* in_sizes, int n_in,
                              void* d_out, int out_size)
{
    const float* first  = (const float*)d_in[0];
    const float* second = (const float*)d_in[1];
    float* out          = (float*)d_out;

    cudaFuncSetAttribute(FunctionCorrelation_17282948399394_kernel,
                         cudaFuncAttributeMaxDynamicSharedMemorySize,
                         (int)SMEM_BYTES);

    dim3 block(GX, TY, 1);
    FunctionCorrelation_17282948399394_kernel<<<NBLOCKS, block, SMEM_BYTES>>>(
        first, second, out);
}

// round 15
// speedup vs baseline: 2.0704x; 1.2657x over previous
#include <cuda_runtime.h>
#include <cuda.h>

// Correlation cost volume (FlowNet-style), MAX_DISP=4 (81 displacements).
// first, second: [B=4, C=128, H=128, W=192] fp32.  out: [B, 81, H, W] fp32,
// out[b,(dy+4)*9+(dx+4),y,x] = (1/C) * sum_c first[b,c,y,x]*second[b,c,y+dy,x+dx]
//
// v11: R7 tile + compute body (best: 72.2us) with TMA (cp.async.bulk.tensor.3d)
// replacing per-thread cp.async: 2 TMA loads/stage from one elected thread,
// HW OOB zero-fill = halo padding (no vmask/secOff), mbarrier double-buffer
// pipeline with ONE __syncthreads per stage.

namespace {
constexpr int Bb = 4, Cc = 128, Hh = 128, Ww = 192;
constexpr int PXT = 4;             // pixels per thread along x
constexpr int GX  = 16;            // thread columns
constexpr int TX  = GX * PXT;      // 64
constexpr int TY  = 8;
constexpr int NT  = GX * TY;       // 128 threads/block
constexpr int CCH = 8;             // channels per stage
constexpr int NST = Cc / CCH;      // 16
constexpr int SROWS = TY + 2;      // 10 second rows per dy-group of 3
constexpr int SW  = TX + 8;        // 72 floats per second row
constexpr int SROW_V4 = SW / 4;    // 18
constexpr int XT  = Ww / TX;       // 3
constexpr int YT  = Hh / TY;       // 16
constexpr int SEC_F = CCH * SROWS * SW;   // 5760 floats = 23040 B (TMA box 72x10x8)
constexpr int FST_F = CCH * TY * TX;      // 4096 floats = 16384 B (TMA box 64x8x8)
constexpr int BUF_F = SEC_F + FST_F;      // 9856 floats; buffer stride 39424 B (128-mult)
constexpr unsigned MBAR_OFF = 2u * BUF_F * 4u;        // mbarriers after the buffers
constexpr unsigned SMEM_BYTES = MBAR_OFF + 128u;      // 78976 B -> 2 blocks/SM
constexpr unsigned STAGE_BYTES = (unsigned)BUF_F * 4u;  // expect_tx per stage
constexpr int NBLOCKS = Bb * XT * YT * 3;  // 576 (1.95 waves @ 2 blocks/SM)
}  // namespace

__device__ __forceinline__ unsigned long long pack2(float x, float y) {
    unsigned long long r;
    asm("mov.b64 %0, {%1, %2};" : "=l"(r) : "f"(x), "f"(y));
    return r;
}
__device__ __forceinline__ void ffma2(unsigned long long& d,
                                      unsigned long long a, unsigned long long b) {
    asm("fma.rn.f32x2 %0, %1, %2, %0;" : "+l"(d) : "l"(a), "l"(b));
}
__device__ __forceinline__ void unpack2(unsigned long long v, float& lo, float& hi) {
    asm("mov.b64 {%0, %1}, %2;" : "=f"(lo), "=f"(hi) : "l"(v));
}
__device__ __forceinline__ void mbar_init(unsigned addr, unsigned count) {
    asm volatile("mbarrier.init.shared.b64 [%0], %1;" :: "r"(addr), "r"(count) : "memory");
}
__device__ __forceinline__ void mbar_expect_tx(unsigned addr, unsigned bytes) {
    asm volatile("mbarrier.arrive.expect_tx.shared.b64 _, [%0], %1;"
                 :: "r"(addr), "r"(bytes) : "memory");
}
__device__ __forceinline__ void mbar_wait(unsigned addr, unsigned parity) {
    asm volatile(
        "{\n\t.reg .pred P;\n"
        "W_%=:\n\t"
        "mbarrier.try_wait.parity.acquire.cta.shared::cta.b64 P, [%0], %1, 0x989680;\n\t"
        "@P bra D_%=;\n\t"
        "bra W_%=;\n"
        "D_%=:\n\t}"
        :: "r"(addr), "r"(parity) : "memory");
}
__device__ __forceinline__ void tma3d(unsigned sdst, const CUtensorMap* tm,
                                      int cx, int cy, int cz, unsigned mbar) {
    asm volatile(
        "cp.async.bulk.tensor.3d.shared::cta.global.tile.mbarrier::complete_tx::bytes "
        "[%0], [%1, {%2, %3, %4}], [%5];"
        :: "r"(sdst), "l"(tm), "r"(cx), "r"(cy), "r"(cz), "r"(mbar) : "memory");
}

__global__ __launch_bounds__(NT, 2)
void FunctionCorrelation_17282948399394_kernel(
    const __grid_constant__ CUtensorMap tmSec,
    const __grid_constant__ CUtensorMap tmFst,
    float* __restrict__ out)
{
    extern __shared__ float smem[];
    const unsigned smem_u32 = (unsigned)__cvta_generic_to_shared(smem);

    const int tx  = threadIdx.x;          // 0..15
    const int ty  = threadIdx.y;          // 0..7
    const int tid = ty * GX + tx;         // 0..127

    int t = blockIdx.x;
    const int g  = t % 3;  t /= 3;        // dy group: dy in {3g-4,3g-3,3g-2}
    const int xt = t % XT; t /= XT;
    const int yt = t % YT; t /= YT;
    const int b  = t;

    const int x0  = xt * TX;
    const int y0  = yt * TY;
    const int ys0 = y0 + 3 * g - 4;       // may be negative: TMA zero-fills OOB
    const int zc0 = b * Cc;               // plane index base (b,ch)

    const unsigned mb0 = smem_u32 + MBAR_OFF;
    const unsigned mb1 = smem_u32 + MBAR_OFF + 8;

    if (tid == 0) { mbar_init(mb0, 1); mbar_init(mb1, 1); }
    __syncthreads();

    auto issue_stage = [&](int st) {      // elected thread only
        const unsigned mb   = (st & 1) ? mb1 : mb0;
        const unsigned base = smem_u32 + (unsigned)(st & 1) * STAGE_BYTES;
        mbar_expect_tx(mb, STAGE_BYTES);
        tma3d(base,                        &tmSec, x0 - 4, ys0, zc0 + st * CCH, mb);
        tma3d(base + (unsigned)SEC_F * 4u, &tmFst, x0,     y0,  zc0 + st * CCH, mb);
    };

    if (tid == 0) { issue_stage(0); issue_stage(1); }

    // ---- accumulators (identical layout to R7) ------------------------------
    unsigned long long acc2[3][5][2];   // even dx=2q: [j][q][pixel-pair]
    float acco[3][4][4];                // odd dx=2o+1: [j][o][pixel]
#pragma unroll
    for (int j = 0; j < 3; j++) {
#pragma unroll
        for (int q = 0; q < 5; q++) { acc2[j][q][0] = 0ull; acc2[j][q][1] = 0ull; }
#pragma unroll
        for (int o = 0; o < 4; o++)
#pragma unroll
            for (int p = 0; p < 4; p++) acco[j][o][p] = 0.f;
    }

#pragma unroll 1
    for (int st = 0; st < NST; st++) {
        mbar_wait((st & 1) ? mb1 : mb0, (unsigned)((st >> 1) & 1));

        const float4* secb = (const float4*)(smem + (st & 1) * BUF_F);
        const float4* fstb = (const float4*)(smem + (st & 1) * BUF_F + SEC_F);

#pragma unroll
        for (int ch = 0; ch < CCH; ch++) {
            const float4 f = fstb[(ch * TY + ty) * (TX / 4) + tx];
            const unsigned long long fp0 = pack2(f.x, f.y);
            const unsigned long long fp1 = pack2(f.z, f.w);
#pragma unroll
            for (int j = 0; j < 3; j++) {
                const float4* sr = secb + (ch * SROWS + ty + j) * SROW_V4 + tx;
                const float4 a = sr[0], c = sr[1], e = sr[2];
                // s[0..11] = a.x a.y a.z a.w  c.x c.y c.z c.w  e.x e.y e.z e.w
                const unsigned long long P0 = pack2(a.x, a.y);
                const unsigned long long P1 = pack2(a.z, a.w);
                const unsigned long long P2 = pack2(c.x, c.y);
                const unsigned long long P3 = pack2(c.z, c.w);
                const unsigned long long P4 = pack2(e.x, e.y);
                const unsigned long long P5 = pack2(e.z, e.w);
                // even dx=2q: pair0 (p0,p1) uses P_q, pair1 (p2,p3) uses P_{q+1}
                ffma2(acc2[j][0][0], fp0, P0);  ffma2(acc2[j][0][1], fp1, P1);
                ffma2(acc2[j][1][0], fp0, P1);  ffma2(acc2[j][1][1], fp1, P2);
                ffma2(acc2[j][2][0], fp0, P2);  ffma2(acc2[j][2][1], fp1, P3);
                ffma2(acc2[j][3][0], fp0, P3);  ffma2(acc2[j][3][1], fp1, P4);
                ffma2(acc2[j][4][0], fp0, P4);  ffma2(acc2[j][4][1], fp1, P5);
                // odd dx=2o+1: acco[j][o][p] += f[p] * s[2o+1+p]
                acco[j][0][0] += f.x * a.y;  acco[j][0][1] += f.y * a.z;
                acco[j][0][2] += f.z * a.w;  acco[j][0][3] += f.w * c.x;
                acco[j][1][0] += f.x * a.w;  acco[j][1][1] += f.y * c.x;
                acco[j][1][2] += f.z * c.y;  acco[j][1][3] += f.w * c.z;
                acco[j][2][0] += f.x * c.y;  acco[j][2][1] += f.y * c.z;
                acco[j][2][2] += f.z * c.w;  acco[j][2][3] += f.w * e.x;
                acco[j][3][0] += f.x * c.w;  acco[j][3][1] += f.y * e.x;
                acco[j][3][2] += f.z * e.y;  acco[j][3][3] += f.w * e.z;
            }
        }

        __syncthreads();   // all warps done reading buffer st&1
        if (st + 2 < NST && tid == 0)
            issue_stage(st + 2);           // refill it; overlaps next compute
    }

    // ---- epilogue: 27 planes x 4 pixels, float4 stores ----------------------
    const float inv = 1.0f / (float)Cc;
    const int x = x0 + tx * PXT;
    const int y = y0 + ty;
#pragma unroll
    for (int j = 0; j < 3; j++) {
        const int dyi = 3 * g + j;
#pragma unroll
        for (int q = 0; q < 5; q++) {              // dx index 2q
            float v0, v1, v2, v3;
            unpack2(acc2[j][q][0], v0, v1);
            unpack2(acc2[j][q][1], v2, v3);
            const int d = dyi * 9 + 2 * q;
            *reinterpret_cast<float4*>(out + ((b * 81 + d) * Hh + y) * Ww + x) =
                make_float4(v0 * inv, v1 * inv, v2 * inv, v3 * inv);
        }
#pragma unroll
        for (int o = 0; o < 4; o++) {              // dx index 2o+1
            const int d = dyi * 9 + 2 * o + 1;
            *reinterpret_cast<float4*>(out + ((b * 81 + d) * Hh + y) * Ww + x) =
                make_float4(acco[j][o][0] * inv, acco[j][o][1] * inv,
                            acco[j][o][2] * inv, acco[j][o][3] * inv);
        }
    }
}

// ---------------------------------------------------------------------------
typedef CUresult (*PFN_tmEncode)(
    CUtensorMap*, CUtensorMapDataType, cuuint32_t, void*,
    const cuuint64_t*, const cuuint64_t*, const cuuint32_t*, const cuuint32_t*,
    CUtensorMapInterleave, CUtensorMapSwizzle, CUtensorMapL2promotion,
    CUtensorMapFloatOOBfill);

static void make_map(PFN_tmEncode enc, CUtensorMap* tm, const void* ptr,
                     unsigned bx, unsigned by, unsigned bz) {
    cuuint64_t dims[3]    = {(cuuint64_t)Ww, (cuuint64_t)Hh,
                             (cuuint64_t)(Bb * Cc)};
    cuuint64_t strides[2] = {(cuuint64_t)Ww * 4u,
                             (cuuint64_t)Hh * Ww * 4u};
    cuuint32_t box[3]     = {bx, by, bz};
    cuuint32_t es[3]      = {1, 1, 1};
    enc(tm, CU_TENSOR_MAP_DATA_TYPE_FLOAT32, 3, (void*)ptr,
        dims, strides, box, es,
        CU_TENSOR_MAP_INTERLEAVE_NONE, CU_TENSOR_MAP_SWIZZLE_NONE,
        CU_TENSOR_MAP_L2_PROMOTION_L2_128B, CU_TENSOR_MAP_FLOAT_OOB_FILL_NONE);
}

extern "C" void kernel_launch(void* const* d_in, const int* in_sizes, int n_in,
                              void* d_out, int out_size)
{
    const float* first  = (const float*)d_in[0];
    const float* second = (const float*)d_in[1];
    float* out          = (float*)d_out;

    static PFN_tmEncode enc = nullptr;
    if (!enc) {
        cudaDriverEntryPointQueryResult qr;
        void* fn = nullptr;
        cudaGetDriverEntryPointByVersion("cuTensorMapEncodeTiled", &fn, 12000,
                                         cudaEnableDefault, &qr);
        enc = (PFN_tmEncode)fn;
    }

    CUtensorMap tmSec, tmFst;
    make_map(enc, &tmSec, second, (unsigned)SW, (unsigned)SROWS, (unsigned)CCH);
    make_map(enc, &tmFst, first,  (unsigned)TX, (unsigned)TY,    (unsigned)CCH);

    cudaFuncSetAttribute(FunctionCorrelation_17282948399394_kernel,
                         cudaFuncAttributeMaxDynamicSharedMemorySize,
                         (int)SMEM_BYTES);

    dim3 block(GX, TY, 1);
    FunctionCorrelation_17282948399394_kernel<<<NBLOCKS, block, SMEM_BYTES>>>(
        tmSec, tmFst, out);
}

// round 17
// speedup vs baseline: 2.1788x; 1.0524x over previous
#include <cuda_runtime.h>
#include <cuda.h>

// Correlation cost volume (FlowNet-style), MAX_DISP=4 (81 displacements).
// first, second: [B=4, C=128, H=128, W=192] fp32.  out: [B, 81, H, W] fp32,
// out[b,(dy+4)*9+(dx+4),y,x] = (1/C) * sum_c first[b,c,y,x]*second[b,c,y+dy,x+dx]
//
// v12: R15 (best: 60.4us) with the per-stage __syncthreads replaced by
// per-buffer EMPTY mbarriers (arrive count = 4 warps): warps decouple and
// skew freely within the 2-deep pipeline; only the TMA producer (tid 0)
// waits for buffer emptiness. Everything else identical to R15.

namespace {
constexpr int Bb = 4, Cc = 128, Hh = 128, Ww = 192;
constexpr int PXT = 4;             // pixels per thread along x
constexpr int GX  = 16;            // thread columns
constexpr int TX  = GX * PXT;      // 64
constexpr int TY  = 8;
constexpr int NT  = GX * TY;       // 128 threads = 4 warps
constexpr int NWARP = NT / 32;     // 4
constexpr int CCH = 8;             // channels per stage
constexpr int NST = Cc / CCH;      // 16
constexpr int SROWS = TY + 2;      // 10 second rows per dy-group of 3
constexpr int SW  = TX + 8;        // 72 floats per second row
constexpr int SROW_V4 = SW / 4;    // 18
constexpr int XT  = Ww / TX;       // 3
constexpr int YT  = Hh / TY;       // 16
constexpr int SEC_F = CCH * SROWS * SW;   // 5760 floats (TMA box 72x10x8)
constexpr int FST_F = CCH * TY * TX;      // 4096 floats (TMA box 64x8x8)
constexpr int BUF_F = SEC_F + FST_F;      // 9856 floats per buffer
constexpr unsigned MBAR_OFF = 2u * BUF_F * 4u;   // full0,full1,empty0,empty1
constexpr unsigned SMEM_BYTES = MBAR_OFF + 128u; // 78976 B -> 2 blocks/SM
constexpr unsigned STAGE_BYTES = (unsigned)BUF_F * 4u;
constexpr int NBLOCKS = Bb * XT * YT * 3;  // 576 (1.95 waves @ 2 blocks/SM)
}  // namespace

__device__ __forceinline__ unsigned long long pack2(float x, float y) {
    unsigned long long r;
    asm("mov.b64 %0, {%1, %2};" : "=l"(r) : "f"(x), "f"(y));
    return r;
}
__device__ __forceinline__ void ffma2(unsigned long long& d,
                                      unsigned long long a, unsigned long long b) {
    asm("fma.rn.f32x2 %0, %1, %2, %0;" : "+l"(d) : "l"(a), "l"(b));
}
__device__ __forceinline__ void unpack2(unsigned long long v, float& lo, float& hi) {
    asm("mov.b64 {%0, %1}, %2;" : "=f"(lo), "=f"(hi) : "l"(v));
}
__device__ __forceinline__ void mbar_init(unsigned addr, unsigned count) {
    asm volatile("mbarrier.init.shared.b64 [%0], %1;" :: "r"(addr), "r"(count) : "memory");
}
__device__ __forceinline__ void mbar_expect_tx(unsigned addr, unsigned bytes) {
    asm volatile("mbarrier.arrive.expect_tx.shared.b64 _, [%0], %1;"
                 :: "r"(addr), "r"(bytes) : "memory");
}
__device__ __forceinline__ void mbar_arrive(unsigned addr) {
    asm volatile("mbarrier.arrive.release.cta.shared::cta.b64 _, [%0];"
                 :: "r"(addr) : "memory");
}
__device__ __forceinline__ void mbar_wait(unsigned addr, unsigned parity) {
    asm volatile(
        "{\n\t.reg .pred P;\n"
        "W_%=:\n\t"
        "mbarrier.try_wait.parity.acquire.cta.shared::cta.b64 P, [%0], %1, 0x989680;\n\t"
        "@P bra D_%=;\n\t"
        "bra W_%=;\n"
        "D_%=:\n\t}"
        :: "r"(addr), "r"(parity) : "memory");
}
__device__ __forceinline__ void tma3d(unsigned sdst, const CUtensorMap* tm,
                                      int cx, int cy, int cz, unsigned mbar) {
    asm volatile(
        "cp.async.bulk.tensor.3d.shared::cta.global.tile.mbarrier::complete_tx::bytes "
        "[%0], [%1, {%2, %3, %4}], [%5];"
        :: "r"(sdst), "l"(tm), "r"(cx), "r"(cy), "r"(cz), "r"(mbar) : "memory");
}

__global__ __launch_bounds__(NT, 2)
void FunctionCorrelation_17282948399394_kernel(
    const __grid_constant__ CUtensorMap tmSec,
    const __grid_constant__ CUtensorMap tmFst,
    float* __restrict__ out)
{
    extern __shared__ float smem[];
    const unsigned smem_u32 = (unsigned)__cvta_generic_to_shared(smem);

    const int tx  = threadIdx.x;          // 0..15
    const int ty  = threadIdx.y;          // 0..7
    const int tid = ty * GX + tx;         // 0..127

    int t = blockIdx.x;
    const int g  = t % 3;  t /= 3;        // dy group: dy in {3g-4,3g-3,3g-2}
    const int xt = t % XT; t /= XT;
    const int yt = t % YT; t /= YT;
    const int b  = t;

    const int x0  = xt * TX;
    const int y0  = yt * TY;
    const int ys0 = y0 + 3 * g - 4;       // may be negative: TMA zero-fills OOB
    const int zc0 = b * Cc;               // plane index base (b,ch)

    const unsigned full0  = smem_u32 + MBAR_OFF;
    const unsigned full1  = smem_u32 + MBAR_OFF + 8;
    const unsigned empty0 = smem_u32 + MBAR_OFF + 16;
    const unsigned empty1 = smem_u32 + MBAR_OFF + 24;

    if (tid == 0) {
        mbar_init(full0, 1);  mbar_init(full1, 1);
        mbar_init(empty0, NWARP); mbar_init(empty1, NWARP);
    }
    __syncthreads();                      // barriers visible before any TMA

    auto issue_stage = [&](int st) {      // producer (tid 0) only
        const unsigned mb   = (st & 1) ? full1 : full0;
        const unsigned base = smem_u32 + (unsigned)(st & 1) * STAGE_BYTES;
        mbar_expect_tx(mb, STAGE_BYTES);
        tma3d(base,                        &tmSec, x0 - 4, ys0, zc0 + st * CCH, mb);
        tma3d(base + (unsigned)SEC_F * 4u, &tmFst, x0,     y0,  zc0 + st * CCH, mb);
    };

    if (tid == 0) { issue_stage(0); issue_stage(1); }

    // ---- accumulators (identical layout to R7/R15) --------------------------
    unsigned long long acc2[3][5][2];   // even dx=2q: [j][q][pixel-pair]
    float acco[3][4][4];                // odd dx=2o+1: [j][o][pixel]
#pragma unroll
    for (int j = 0; j < 3; j++) {
#pragma unroll
        for (int q = 0; q < 5; q++) { acc2[j][q][0] = 0ull; acc2[j][q][1] = 0ull; }
#pragma unroll
        for (int o = 0; o < 4; o++)
#pragma unroll
            for (int p = 0; p < 4; p++) acco[j][o][p] = 0.f;
    }

#pragma unroll 1
    for (int st = 0; st < NST; st++) {
        const unsigned par = (unsigned)((st >> 1) & 1);   // round parity
        mbar_wait((st & 1) ? full1 : full0, par);

        const float4* secb = (const float4*)(smem + (st & 1) * BUF_F);
        const float4* fstb = (const float4*)(smem + (st & 1) * BUF_F + SEC_F);

#pragma unroll
        for (int ch = 0; ch < CCH; ch++) {
            const float4 f = fstb[(ch * TY + ty) * (TX / 4) + tx];
            const unsigned long long fp0 = pack2(f.x, f.y);
            const unsigned long long fp1 = pack2(f.z, f.w);
#pragma unroll
            for (int j = 0; j < 3; j++) {
                const float4* sr = secb + (ch * SROWS + ty + j) * SROW_V4 + tx;
                const float4 a = sr[0], c = sr[1], e = sr[2];
                // s[0..11] = a.x a.y a.z a.w  c.x c.y c.z c.w  e.x e.y e.z e.w
                const unsigned long long P0 = pack2(a.x, a.y);
                const unsigned long long P1 = pack2(a.z, a.w);
                const unsigned long long P2 = pack2(c.x, c.y);
                const unsigned long long P3 = pack2(c.z, c.w);
                const unsigned long long P4 = pack2(e.x, e.y);
                const unsigned long long P5 = pack2(e.z, e.w);
                // even dx=2q: pair0 (p0,p1) uses P_q, pair1 (p2,p3) uses P_{q+1}
                ffma2(acc2[j][0][0], fp0, P0);  ffma2(acc2[j][0][1], fp1, P1);
                ffma2(acc2[j][1][0], fp0, P1);  ffma2(acc2[j][1][1], fp1, P2);
                ffma2(acc2[j][2][0], fp0, P2);  ffma2(acc2[j][2][1], fp1, P3);
                ffma2(acc2[j][3][0], fp0, P3);  ffma2(acc2[j][3][1], fp1, P4);
                ffma2(acc2[j][4][0], fp0, P4);  ffma2(acc2[j][4][1], fp1, P5);
                // odd dx=2o+1: acco[j][o][p] += f[p] * s[2o+1+p]
                acco[j][0][0] += f.x * a.y;  acco[j][0][1] += f.y * a.z;
                acco[j][0][2] += f.z * a.w;  acco[j][0][3] += f.w * c.x;
                acco[j][1][0] += f.x * a.w;  acco[j][1][1] += f.y * c.x;
                acco[j][1][2] += f.z * c.y;  acco[j][1][3] += f.w * c.z;
                acco[j][2][0] += f.x * c.y;  acco[j][2][1] += f.y * c.z;
                acco[j][2][2] += f.z * c.w;  acco[j][2][3] += f.w * e.x;
                acco[j][3][0] += f.x * c.w;  acco[j][3][1] += f.y * e.x;
                acco[j][3][2] += f.z * e.y;  acco[j][3][3] += f.w * e.z;
            }
        }

        // this warp is done reading buffer st&1: arrive on its empty barrier
        __syncwarp();
        if ((tid & 31) == 0)
            mbar_arrive((st & 1) ? empty1 : empty0);

        // producer: once all 4 warps arrived, refill this buffer with st+2
        if (tid == 0 && st + 2 < NST) {
            mbar_wait((st & 1) ? empty1 : empty0, par);
            issue_stage(st + 2);
        }
    }

    // ---- epilogue: 27 planes x 4 pixels, float4 stores ----------------------
    const float inv = 1.0f / (float)Cc;
    const int x = x0 + tx * PXT;
    const int y = y0 + ty;
#pragma unroll
    for (int j = 0; j < 3; j++) {
        const int dyi = 3 * g + j;
#pragma unroll
        for (int q = 0; q < 5; q++) {              // dx index 2q
            float v0, v1, v2, v3;
            unpack2(acc2[j][q][0], v0, v1);
            unpack2(acc2[j][q][1], v2, v3);
            const int d = dyi * 9 + 2 * q;
            *reinterpret_cast<float4*>(out + ((b * 81 + d) * Hh + y) * Ww + x) =
                make_float4(v0 * inv, v1 * inv, v2 * inv, v3 * inv);
        }
#pragma unroll
        for (int o = 0; o < 4; o++) {              // dx index 2o+1
            const int d = dyi * 9 + 2 * o + 1;
            *reinterpret_cast<float4*>(out + ((b * 81 + d) * Hh + y) * Ww + x) =
                make_float4(acco[j][o][0] * inv, acco[j][o][1] * inv,
                            acco[j][o][2] * inv, acco[j][o][3] * inv);
        }
    }
}

// ---------------------------------------------------------------------------
typedef CUresult (*PFN_tmEncode)(
    CUtensorMap*, CUtensorMapDataType, cuuint32_t, void*,
    const cuuint64_t*, const cuuint64_t*, const cuuint32_t*, const cuuint32_t*,
    CUtensorMapInterleave, CUtensorMapSwizzle, CUtensorMapL2promotion,
    CUtensorMapFloatOOBfill);

static void make_map(PFN_tmEncode enc, CUtensorMap* tm, const void* ptr,
                     unsigned bx, unsigned by, unsigned bz) {
    cuuint64_t dims[3]    = {(cuuint64_t)Ww, (cuuint64_t)Hh,
                             (cuuint64_t)(Bb * Cc)};
    cuuint64_t strides[2] = {(cuuint64_t)Ww * 4u,
                             (cuuint64_t)Hh * Ww * 4u};
    cuuint32_t box[3]     = {bx, by, bz};
    cuuint32_t es[3]      = {1, 1, 1};
    enc(tm, CU_TENSOR_MAP_DATA_TYPE_FLOAT32, 3, (void*)ptr,
        dims, strides, box, es,
        CU_TENSOR_MAP_INTERLEAVE_NONE, CU_TENSOR_MAP_SWIZZLE_NONE,
        CU_TENSOR_MAP_L2_PROMOTION_L2_128B, CU_TENSOR_MAP_FLOAT_OOB_FILL_NONE);
}

extern "C" void kernel_launch(void* const* d_in, const int* in_sizes, int n_in,
                              void* d_out, int out_size)
{
    const float* first  = (const float*)d_in[0];
    const float* second = (const float*)d_in[1];
    float* out          = (float*)d_out;

    static PFN_tmEncode enc = nullptr;
    if (!enc) {
        cudaDriverEntryPointQueryResult qr;
        void* fn = nullptr;
        cudaGetDriverEntryPointByVersion("cuTensorMapEncodeTiled", &fn, 12000,
                                         cudaEnableDefault, &qr);
        enc = (PFN_tmEncode)fn;
    }

    CUtensorMap tmSec, tmFst;
    make_map(enc, &tmSec, second, (unsigned)SW, (unsigned)SROWS, (unsigned)CCH);
    make_map(enc, &tmFst, first,  (unsigned)TX, (unsigned)TY,    (unsigned)CCH);

    cudaFuncSetAttribute(FunctionCorrelation_17282948399394_kernel,
                         cudaFuncAttributeMaxDynamicSharedMemorySize,
                         (int)SMEM_BYTES);

    dim3 block(GX, TY, 1);
    FunctionCorrelation_17282948399394_kernel<<<NBLOCKS, block, SMEM_BYTES>>>(
        tmSec, tmFst, out);
}